// round 2
// baseline (speedup 1.0000x reference)
#include <cuda_runtime.h>
#include <cuda_bf16.h>
#include <cstdint>

#define MAXN 100000
#define MAXE 500000

// ------------------------- scratch (device globals, no mallocs) -------------
__device__ float g_Ps[(size_t)MAXN * 256];   // src-side proj: [Wae_h | War_h]
__device__ float g_Pt[(size_t)MAXN * 256];   // dst-side proj: [Wae_r | War_r]
__device__ float g_attn[(size_t)MAXN * 128]; // attention aggregate
__device__ float g_mean[(size_t)MAXN * 128]; // mean aggregate (sum, divided later)
__device__ float g_cnt[MAXN];
__device__ float g_max0[MAXN], g_max1[MAXN];
__device__ float g_sum0[MAXN], g_sum1[MAXN];
__device__ float g_logit0[MAXE], g_logit1[MAXE];
__device__ float g_Bmat[128 * 512];          // fused pre-projection weight
__device__ float g_bias[256];                // [bae | bar]
__device__ float g_wv[256];                  // [w0w | w1w]

// ------------------------- fast math ---------------------------------------
__device__ __forceinline__ float fast_tanh(float x) {
    // tanh(x) = 1 - 2/(exp(2x)+1), exp via ex2.approx. rel err ~1e-6.
    float e;
    asm("ex2.approx.f32 %0, %1;" : "=f"(e) : "f"(x * 2.885390082f)); // 2*log2(e)
    float r;
    asm("rcp.approx.f32 %0, %1;" : "=f"(r) : "f"(e + 1.0f));
    return fmaf(-2.0f, r, 1.0f);
}

__device__ __forceinline__ float fast_exp(float x) {
    float e;
    asm("ex2.approx.f32 %0, %1;" : "=f"(e) : "f"(x * 1.4426950408889634f));
    return e;
}

// ------------------------- init --------------------------------------------
__global__ void zero_all(int N) {
    size_t stride = (size_t)gridDim.x * blockDim.x;
    size_t i = (size_t)blockIdx.x * blockDim.x + threadIdx.x;
    size_t n4 = (size_t)N * 32;
    float4 z = make_float4(0.f, 0.f, 0.f, 0.f);
    float4* a4 = (float4*)g_attn;
    float4* m4 = (float4*)g_mean;
    for (size_t j = i; j < n4; j += stride) { a4[j] = z; m4[j] = z; }
    for (size_t j = i; j < (size_t)N; j += stride) {
        g_cnt[j] = 0.f; g_max0[j] = 0.f; g_max1[j] = 0.f;
        g_sum0[j] = 0.f; g_sum1[j] = 0.f;
    }
}

// Build combined pre-projection weight + bias/weight vectors.
// Ps[:,0:128)   = emb @ Wae[128:256,:]  (h-side of entity attention)
// Ps[:,128:256) = emb @ War[0:128,:]    (h-side of relation attention)
// Pt[:,0:128)   = emb @ Wae[0:128,:]    (r-side of entity attention)
// Pt[:,128:256) = emb @ War[128:256,:]  (r-side of relation attention)
__global__ void prep_kernel(const float* __restrict__ Wae, const float* __restrict__ War,
                            const float* __restrict__ bae, const float* __restrict__ bar,
                            const float* __restrict__ w0w, const float* __restrict__ w1w) {
    int i = blockIdx.x * blockDim.x + threadIdx.x;
    if (i < 128 * 512) {
        int k = i >> 9;
        int c = i & 511;
        float v;
        if (c < 128)       v = Wae[(128 + k) * 128 + c];
        else if (c < 256)  v = War[k * 128 + (c - 128)];
        else if (c < 384)  v = Wae[k * 128 + (c - 256)];
        else               v = War[(128 + k) * 128 + (c - 384)];
        g_Bmat[i] = v;
    }
    if (i < 128) {
        g_bias[i] = bae[i];       g_bias[128 + i] = bar[i];
        g_wv[i]   = w0w[i];       g_wv[128 + i]   = w1w[i];
    }
}

// ------------------------- pre-projection GEMM -----------------------------
// C(N x 512) = A(N x 128) @ g_Bmat(128 x 512), tiled 128x128, 256 threads.
__global__ __launch_bounds__(256) void gemm_pre(const float* __restrict__ A, int M) {
    extern __shared__ float sm[];
    float* As = sm;            // k-major: As[k*128 + row]
    float* Bs = sm + 16384;    // Bs[k*128 + col]
    int tid = threadIdx.x;
    int rowBase = blockIdx.x * 128;
    int colBase = blockIdx.y * 128;

    const float4* A4 = (const float4*)A;
#pragma unroll
    for (int i = 0; i < 16; i++) {
        int idx = tid + i * 256;      // 0..4095
        int row = idx >> 5;
        int k4  = idx & 31;
        float4 v = make_float4(0.f, 0.f, 0.f, 0.f);
        int grow = rowBase + row;
        if (grow < M) v = A4[(size_t)grow * 32 + k4];
        As[(k4 * 4 + 0) * 128 + row] = v.x;
        As[(k4 * 4 + 1) * 128 + row] = v.y;
        As[(k4 * 4 + 2) * 128 + row] = v.z;
        As[(k4 * 4 + 3) * 128 + row] = v.w;
    }
#pragma unroll
    for (int i = 0; i < 16; i++) {
        int idx = tid + i * 256;
        int k  = idx >> 5;
        int c4 = idx & 31;
        *(float4*)(Bs + k * 128 + c4 * 4) =
            *(const float4*)(g_Bmat + k * 512 + colBase + c4 * 4);
    }
    __syncthreads();

    int ty = tid >> 4, tx = tid & 15;
    float acc[8][8];
#pragma unroll
    for (int i = 0; i < 8; i++)
#pragma unroll
        for (int j = 0; j < 8; j++) acc[i][j] = 0.f;

#pragma unroll
    for (int k = 0; k < 128; k++) {
        float a[8], b[8];
        *(float4*)(a)     = *(float4*)(As + k * 128 + ty * 8);
        *(float4*)(a + 4) = *(float4*)(As + k * 128 + ty * 8 + 4);
        *(float4*)(b)     = *(float4*)(Bs + k * 128 + tx * 8);
        *(float4*)(b + 4) = *(float4*)(Bs + k * 128 + tx * 8 + 4);
#pragma unroll
        for (int i = 0; i < 8; i++)
#pragma unroll
            for (int j = 0; j < 8; j++) acc[i][j] = fmaf(a[i], b[j], acc[i][j]);
    }

    float* Cbase;
    int ccol;
    if (blockIdx.y < 2) { Cbase = g_Ps; ccol = colBase; }
    else                { Cbase = g_Pt; ccol = colBase - 256; }
#pragma unroll
    for (int i = 0; i < 8; i++) {
        int grow = rowBase + ty * 8 + i;
        if (grow >= M) continue;
        float* dst = Cbase + (size_t)grow * 256 + ccol + tx * 8;
        *(float4*)(dst)     = make_float4(acc[i][0], acc[i][1], acc[i][2], acc[i][3]);
        *(float4*)(dst + 4) = make_float4(acc[i][4], acc[i][5], acc[i][6], acc[i][7]);
    }
}

// ------------------------- edge passes -------------------------------------
// Per-edge logits for both attention heads. Warp per edge.
__global__ void edge_logits(const int* __restrict__ src, const int* __restrict__ dst, int E,
                            const float* __restrict__ w0b, const float* __restrict__ w1b) {
    int gw = (int)(((size_t)blockIdx.x * blockDim.x + threadIdx.x) >> 5);
    int lane = threadIdx.x & 31;
    if (gw >= E) return;
    int s = src[gw], t = dst[gw];
    const float4* ps = (const float4*)(g_Ps + (size_t)s * 256);
    const float4* pt = (const float4*)(g_Pt + (size_t)t * 256);
    const float4* bi = (const float4*)g_bias;
    const float4* wv = (const float4*)g_wv;

    float4 a = ps[lane], b = pt[lane], c = bi[lane], w = wv[lane];
    float s0 = fast_tanh(a.x + b.x + c.x) * w.x
             + fast_tanh(a.y + b.y + c.y) * w.y
             + fast_tanh(a.z + b.z + c.z) * w.z
             + fast_tanh(a.w + b.w + c.w) * w.w;

    a = ps[32 + lane]; b = pt[32 + lane]; c = bi[32 + lane]; w = wv[32 + lane];
    float s1 = fast_tanh(a.x + b.x + c.x) * w.x
             + fast_tanh(a.y + b.y + c.y) * w.y
             + fast_tanh(a.z + b.z + c.z) * w.z
             + fast_tanh(a.w + b.w + c.w) * w.w;

#pragma unroll
    for (int o = 16; o; o >>= 1) {
        s0 += __shfl_xor_sync(0xFFFFFFFFu, s0, o);
        s1 += __shfl_xor_sync(0xFFFFFFFFu, s1, o);
    }
    if (lane == 0) {
        float e0 = s0 + w0b[0];
        float e1 = s1 + w1b[0];
        g_logit0[gw] = e0;
        g_logit1[gw] = e1;
        // max is clamped at 0 (torch include_self over zeros); int-bit atomicMax
        // valid since both stored (0) and candidates (>0) are non-negative.
        if (e0 > 0.f) atomicMax((int*)(g_max0 + s), __float_as_int(e0));
        if (e1 > 0.f) atomicMax((int*)(g_max1 + t), __float_as_int(e1));
    }
}

__global__ void edge_exp(const int* __restrict__ src, const int* __restrict__ dst, int E) {
    int e = blockIdx.x * blockDim.x + threadIdx.x;
    if (e >= E) return;
    int s = src[e], t = dst[e];
    float p0 = fast_exp(g_logit0[e] - g_max0[s]);
    float p1 = fast_exp(g_logit1[e] - g_max1[t]);
    g_logit0[e] = p0;
    g_logit1[e] = p1;
    atomicAdd(g_sum0 + s, p0);
    atomicAdd(g_sum1 + t, p1);
}

// attn_agg[s] += a0 * emb[t];  attn_agg[t] += a1 * emb[s].  Warp per edge.
__global__ void edge_scatter(const int* __restrict__ src, const int* __restrict__ dst, int E,
                             const float* __restrict__ emb) {
    int gw = (int)(((size_t)blockIdx.x * blockDim.x + threadIdx.x) >> 5);
    int lane = threadIdx.x & 31;
    if (gw >= E) return;
    int s = src[gw], t = dst[gw];
    float a0 = __fdividef(g_logit0[gw], g_sum0[s] + 1e-9f);
    float a1 = __fdividef(g_logit1[gw], g_sum1[t] + 1e-9f);
    const float4* emb4 = (const float4*)emb;

    float4 r = emb4[(size_t)t * 32 + lane];
    float* d0 = g_attn + (size_t)s * 128 + lane * 4;
    atomicAdd(d0 + 0, a0 * r.x); atomicAdd(d0 + 1, a0 * r.y);
    atomicAdd(d0 + 2, a0 * r.z); atomicAdd(d0 + 3, a0 * r.w);

    float4 h = emb4[(size_t)s * 32 + lane];
    float* d1 = g_attn + (size_t)t * 128 + lane * 4;
    atomicAdd(d1 + 0, a1 * h.x); atomicAdd(d1 + 1, a1 * h.y);
    atomicAdd(d1 + 2, a1 * h.z); atomicAdd(d1 + 3, a1 * h.w);
}

// mean_agg[s] += emb[t]; cnt[s] += 1.  Warp per edge.
__global__ void mean_scatter(const int* __restrict__ src, const int* __restrict__ dst, int E,
                             const float* __restrict__ emb) {
    int gw = (int)(((size_t)blockIdx.x * blockDim.x + threadIdx.x) >> 5);
    int lane = threadIdx.x & 31;
    if (gw >= E) return;
    int s = src[gw], t = dst[gw];
    const float4* emb4 = (const float4*)emb;
    float4 v = emb4[(size_t)t * 32 + lane];
    float* d0 = g_mean + (size_t)s * 128 + lane * 4;
    atomicAdd(d0 + 0, v.x); atomicAdd(d0 + 1, v.y);
    atomicAdd(d0 + 2, v.z); atomicAdd(d0 + 3, v.w);
    if (lane == 0) atomicAdd(g_cnt + s, 1.0f);
}

// ------------------------- fused output GEMM --------------------------------
// out = tanh(emb@W1+b1) + tanh(attn@W2+b2) + tanh((mean/cnt)@W3+b3)
__global__ __launch_bounds__(256) void gemm_out(const float* __restrict__ emb,
                                                const float* __restrict__ W1, const float* __restrict__ b1,
                                                const float* __restrict__ W2, const float* __restrict__ b2,
                                                const float* __restrict__ W3, const float* __restrict__ b3,
                                                float* __restrict__ out, int M) {
    extern __shared__ float sm[];
    float* As = sm;
    float* Bs = sm + 16384;
    int tid = threadIdx.x;
    int rowBase = blockIdx.x * 128;
    int ty = tid >> 4, tx = tid & 15;

    float res[8][8];
#pragma unroll
    for (int i = 0; i < 8; i++)
#pragma unroll
        for (int j = 0; j < 8; j++) res[i][j] = 0.f;

    const float* Asrc[3] = { emb, g_attn, g_mean };
    const float* Wsrc[3] = { W1, W2, W3 };
    const float* bsrc[3] = { b1, b2, b3 };

    for (int term = 0; term < 3; term++) {
        const float4* A4 = (const float4*)Asrc[term];
#pragma unroll
        for (int i = 0; i < 16; i++) {
            int idx = tid + i * 256;
            int row = idx >> 5;
            int k4  = idx & 31;
            float4 v = make_float4(0.f, 0.f, 0.f, 0.f);
            int grow = rowBase + row;
            if (grow < M) {
                v = A4[(size_t)grow * 32 + k4];
                if (term == 2) {
                    float rc = 1.0f / fmaxf(g_cnt[grow], 1.0f);
                    v.x *= rc; v.y *= rc; v.z *= rc; v.w *= rc;
                }
            }
            As[(k4 * 4 + 0) * 128 + row] = v.x;
            As[(k4 * 4 + 1) * 128 + row] = v.y;
            As[(k4 * 4 + 2) * 128 + row] = v.z;
            As[(k4 * 4 + 3) * 128 + row] = v.w;
        }
        const float* W = Wsrc[term];
#pragma unroll
        for (int i = 0; i < 16; i++) {
            int idx = tid + i * 256;
            int k  = idx >> 5;
            int c4 = idx & 31;
            *(float4*)(Bs + k * 128 + c4 * 4) = *(const float4*)(W + k * 128 + c4 * 4);
        }
        __syncthreads();

        float acc[8][8];
#pragma unroll
        for (int i = 0; i < 8; i++)
#pragma unroll
            for (int j = 0; j < 8; j++) acc[i][j] = 0.f;

#pragma unroll
        for (int k = 0; k < 128; k++) {
            float a[8], b[8];
            *(float4*)(a)     = *(float4*)(As + k * 128 + ty * 8);
            *(float4*)(a + 4) = *(float4*)(As + k * 128 + ty * 8 + 4);
            *(float4*)(b)     = *(float4*)(Bs + k * 128 + tx * 8);
            *(float4*)(b + 4) = *(float4*)(Bs + k * 128 + tx * 8 + 4);
#pragma unroll
            for (int i = 0; i < 8; i++)
#pragma unroll
                for (int j = 0; j < 8; j++) acc[i][j] = fmaf(a[i], b[j], acc[i][j]);
        }

        float bc[8];
#pragma unroll
        for (int j = 0; j < 8; j++) bc[j] = bsrc[term][tx * 8 + j];
#pragma unroll
        for (int i = 0; i < 8; i++)
#pragma unroll
            for (int j = 0; j < 8; j++) res[i][j] += fast_tanh(acc[i][j] + bc[j]);

        __syncthreads();
    }

#pragma unroll
    for (int i = 0; i < 8; i++) {
        int grow = rowBase + ty * 8 + i;
        if (grow >= M) continue;
        float* dst = out + (size_t)grow * 128 + tx * 8;
        *(float4*)(dst)     = make_float4(res[i][0], res[i][1], res[i][2], res[i][3]);
        *(float4*)(dst + 4) = make_float4(res[i][4], res[i][5], res[i][6], res[i][7]);
    }
}

// ------------------------- launch ------------------------------------------
extern "C" void kernel_launch(void* const* d_in, const int* in_sizes, int n_in,
                              void* d_out, int out_size) {
    const float* emb = (const float*)d_in[0];
    const float* Wae = (const float*)d_in[1];
    const float* bae = (const float*)d_in[2];
    const float* w0w = (const float*)d_in[3];
    const float* w0b = (const float*)d_in[4];
    const float* War = (const float*)d_in[5];
    const float* bar = (const float*)d_in[6];
    const float* w1w = (const float*)d_in[7];
    const float* w1b = (const float*)d_in[8];
    const float* W1  = (const float*)d_in[9];
    const float* b1  = (const float*)d_in[10];
    const float* W2  = (const float*)d_in[11];
    const float* b2  = (const float*)d_in[12];
    const float* W3  = (const float*)d_in[13];
    const float* b3  = (const float*)d_in[14];
    const int* er_src = (const int*)d_in[15];
    const int* er_dst = (const int*)d_in[16];
    const int* ee_src = (const int*)d_in[17];
    const int* ee_dst = (const int*)d_in[18];
    const int* rr_src = (const int*)d_in[19];
    const int* rr_dst = (const int*)d_in[20];

    int N   = in_sizes[0] / 128;
    int Eer = in_sizes[15];
    int Eee = in_sizes[17];
    int Err = in_sizes[19];
    float* out = (float*)d_out;

    cudaFuncSetAttribute(gemm_pre, cudaFuncAttributeMaxDynamicSharedMemorySize, 131072);
    cudaFuncSetAttribute(gemm_out, cudaFuncAttributeMaxDynamicSharedMemorySize, 131072);

    zero_all<<<2048, 256>>>(N);
    prep_kernel<<<(128 * 512 + 255) / 256, 256>>>(Wae, War, bae, bar, w0w, w1w);

    dim3 gpre((N + 127) / 128, 4);
    gemm_pre<<<gpre, 256, 131072>>>(emb, N);

    int wblk_er = (Eer + 7) / 8;  // 8 warps per 256-thread block
    edge_logits<<<wblk_er, 256>>>(er_src, er_dst, Eer, w0b, w1b);
    edge_exp<<<(Eer + 255) / 256, 256>>>(er_src, er_dst, Eer);
    edge_scatter<<<wblk_er, 256>>>(er_src, er_dst, Eer, emb);

    mean_scatter<<<(Eee + 7) / 8, 256>>>(ee_src, ee_dst, Eee, emb);
    mean_scatter<<<(Err + 7) / 8, 256>>>(rr_src, rr_dst, Err, emb);

    gemm_out<<<dim3((N + 127) / 128, 1), 256, 131072>>>(emb, W1, b1, W2, b2, W3, b3, out, N);
}

// round 4
// speedup vs baseline: 2.3186x; 2.3186x over previous
#include <cuda_runtime.h>
#include <cuda_bf16.h>
#include <cstdint>

#define MAXN 100000
#define MAXE 500000

// ------------------------- scratch (device globals, no mallocs) -------------
__device__ float g_Ps[(size_t)MAXN * 256];   // src-side proj: [Wae_h | War_h]
__device__ float g_Pt[(size_t)MAXN * 256];   // dst-side proj: [Wae_r | War_r]
__device__ float g_attn[(size_t)MAXN * 128]; // attention aggregate
__device__ float g_mean[(size_t)MAXN * 128]; // mean aggregate (sum, divided later)
__device__ float g_cnt[MAXN];
__device__ float g_max0[MAXN], g_max1[MAXN];
__device__ float g_sum0[MAXN], g_sum1[MAXN];
__device__ float g_logit0[MAXE], g_logit1[MAXE];
__device__ float g_bias[256];                // [bae | bar]
__device__ float g_wv[256];                  // [w0w | w1w]
// bf16 weight tiles, B^T layout [n][k] (n = output col, k = input dim), hi/lo split
__device__ __align__(16) __nv_bfloat16 g_BpreH[4 * 16384];
__device__ __align__(16) __nv_bfloat16 g_BpreL[4 * 16384];
__device__ __align__(16) __nv_bfloat16 g_BoutH[3 * 16384];
__device__ __align__(16) __nv_bfloat16 g_BoutL[3 * 16384];

// ------------------------- mma.sync helpers (baseline PTX, no 'a' features) -
__device__ __forceinline__ uint32_t smem_u32(const void* p) {
    uint32_t a;
    asm("{ .reg .u64 t; cvta.to.shared.u64 t, %1; cvt.u32.u64 %0, t; }" : "=r"(a) : "l"(p));
    return a;
}

#define LDM_X4(r, addr) \
    asm volatile("ldmatrix.sync.aligned.m8n8.x4.shared.b16 {%0,%1,%2,%3}, [%4];" \
        : "=r"((r)[0]), "=r"((r)[1]), "=r"((r)[2]), "=r"((r)[3]) : "r"(addr))

#define LDM_X2(r, addr) \
    asm volatile("ldmatrix.sync.aligned.m8n8.x2.shared.b16 {%0,%1}, [%2];" \
        : "=r"((r)[0]), "=r"((r)[1]) : "r"(addr))

#define MMA_BF16(c, a, b) \
    asm volatile("mma.sync.aligned.m16n8k16.row.col.f32.bf16.bf16.f32 " \
        "{%0,%1,%2,%3}, {%4,%5,%6,%7}, {%8,%9}, {%0,%1,%2,%3};" \
        : "+f"((c)[0]), "+f"((c)[1]), "+f"((c)[2]), "+f"((c)[3]) \
        : "r"((a)[0]), "r"((a)[1]), "r"((a)[2]), "r"((a)[3]), "r"((b)[0]), "r"((b)[1]))

// ------------------------- fast math ---------------------------------------
__device__ __forceinline__ float fast_tanh(float x) {
    float e;
    asm("ex2.approx.f32 %0, %1;" : "=f"(e) : "f"(x * 2.885390082f));
    float r;
    asm("rcp.approx.f32 %0, %1;" : "=f"(r) : "f"(e + 1.0f));
    return fmaf(-2.0f, r, 1.0f);
}

__device__ __forceinline__ float fast_exp(float x) {
    float e;
    asm("ex2.approx.f32 %0, %1;" : "=f"(e) : "f"(x * 1.4426950408889634f));
    return e;
}

// ------------------------- init --------------------------------------------
__global__ void zero_all(int N) {
    size_t stride = (size_t)gridDim.x * blockDim.x;
    size_t i = (size_t)blockIdx.x * blockDim.x + threadIdx.x;
    size_t n4 = (size_t)N * 32;
    float4 z = make_float4(0.f, 0.f, 0.f, 0.f);
    float4* a4 = (float4*)g_attn;
    float4* m4 = (float4*)g_mean;
    for (size_t j = i; j < n4; j += stride) { a4[j] = z; m4[j] = z; }
    for (size_t j = i; j < (size_t)N; j += stride) {
        g_cnt[j] = 0.f; g_max0[j] = 0.f; g_max1[j] = 0.f;
        g_sum0[j] = 0.f; g_sum1[j] = 0.f;
    }
}

// Build bf16 hi/lo B^T weight tiles + bias/weight vectors.
// Fused pre-GEMM weight columns cc in [0,512):
//  y0 (Ps 0..127)  : Wae[(128+k)*128 + cc]        (h-side of entity attention)
//  y1 (Ps 128..255): War[k*128 + (cc-128)]        (h-side of relation attention)
//  y2 (Pt 0..127)  : Wae[k*128 + (cc-256)]        (r-side of entity attention)
//  y3 (Pt 128..255): War[(128+k)*128 + (cc-384)]  (r-side of relation attention)
__global__ void prep_kernel(const float* __restrict__ Wae, const float* __restrict__ War,
                            const float* __restrict__ bae, const float* __restrict__ bar,
                            const float* __restrict__ w0w, const float* __restrict__ w1w,
                            const float* __restrict__ W1, const float* __restrict__ W2,
                            const float* __restrict__ W3) {
    int i = blockIdx.x * blockDim.x + threadIdx.x;
    if (i < 65536) {
        int y = i >> 14, r = i & 16383, k = r >> 7, n = r & 127;
        int cc = (y << 7) + n;
        float v;
        if (y == 0)      v = Wae[(128 + k) * 128 + cc];
        else if (y == 1) v = War[k * 128 + (cc - 128)];
        else if (y == 2) v = Wae[k * 128 + (cc - 256)];
        else             v = War[(128 + k) * 128 + (cc - 384)];
        __nv_bfloat16 h = __float2bfloat16(v);
        __nv_bfloat16 l = __float2bfloat16(v - __bfloat162float(h));
        g_BpreH[y * 16384 + n * 128 + k] = h;
        g_BpreL[y * 16384 + n * 128 + k] = l;
    } else if (i < 65536 + 49152) {
        int j = i - 65536;
        int t = j >> 14, r = j & 16383, k = r >> 7, n = r & 127;
        const float* W = (t == 0) ? W1 : (t == 1) ? W2 : W3;
        float v = W[k * 128 + n];
        __nv_bfloat16 h = __float2bfloat16(v);
        __nv_bfloat16 l = __float2bfloat16(v - __bfloat162float(h));
        g_BoutH[t * 16384 + n * 128 + k] = h;
        g_BoutL[t * 16384 + n * 128 + k] = l;
    }
    if (i < 128) {
        g_bias[i] = bae[i];  g_bias[128 + i] = bar[i];
        g_wv[i]   = w0w[i];  g_wv[128 + i]   = w1w[i];
    }
}

// ------------------------- shared GEMM machinery ----------------------------
// smem: A_hi/A_lo [128][136] bf16, B_hi/B_lo (B^T, [n][k]) [128][136] bf16.
#define SLD   136                 // bf16 row stride (272 B, 16B-aligned, bank-staggered)
#define TILE_BF (128 * SLD)       // bf16 elements per tile
#define OF_AH 0
#define OF_AL (TILE_BF)
#define OF_BH (2 * TILE_BF)
#define OF_BL (3 * TILE_BF)
#define SMEM_GEMM (4 * TILE_BF * 2)          // 139264 B
#define SMEM_GEMM_OUT (SMEM_GEMM + 1536)     // + 3x128 bias floats

__device__ __forceinline__ uint32_t b2u(__nv_bfloat162 v) {
    return *reinterpret_cast<uint32_t*>(&v);
}

// stage a 128x128 fp32 A tile into smem as bf16 hi/lo (per-row scale optional)
__device__ __forceinline__ void stage_A(__nv_bfloat16* sAh, __nv_bfloat16* sAl,
                                        const float* __restrict__ A, int rowBase, int M,
                                        const float* __restrict__ cnt, int tid) {
#pragma unroll
    for (int i = 0; i < 16; i++) {
        int idx = tid + i * 256;          // 0..4095
        int row = idx >> 5, q = idx & 31; // q = float4 index within row
        float4 v = make_float4(0.f, 0.f, 0.f, 0.f);
        int gr = rowBase + row;
        if (gr < M) {
            v = ((const float4*)A)[(size_t)gr * 32 + q];
            if (cnt) {
                float rc = 1.0f / fmaxf(cnt[gr], 1.0f);
                v.x *= rc; v.y *= rc; v.z *= rc; v.w *= rc;
            }
        }
        __nv_bfloat162 h01 = __floats2bfloat162_rn(v.x, v.y);
        __nv_bfloat162 h23 = __floats2bfloat162_rn(v.z, v.w);
        __nv_bfloat162 l01 = __floats2bfloat162_rn(v.x - __bfloat162float(h01.x),
                                                   v.y - __bfloat162float(h01.y));
        __nv_bfloat162 l23 = __floats2bfloat162_rn(v.z - __bfloat162float(h23.x),
                                                   v.w - __bfloat162float(h23.y));
        *(uint2*)(sAh + row * SLD + q * 4) = make_uint2(b2u(h01), b2u(h23));
        *(uint2*)(sAl + row * SLD + q * 4) = make_uint2(b2u(l01), b2u(l23));
    }
}

// stage a 128x128 bf16 B^T tile (already split) into smem
__device__ __forceinline__ void stage_B(__nv_bfloat16* sBh, __nv_bfloat16* sBl,
                                        const __nv_bfloat16* __restrict__ BH,
                                        const __nv_bfloat16* __restrict__ BL, int tid) {
    const int4* srcH = (const int4*)BH;
    const int4* srcL = (const int4*)BL;
    int4* dH = (int4*)sBh;
    int4* dL = (int4*)sBl;
#pragma unroll
    for (int i = 0; i < 8; i++) {
        int idx = tid + i * 256;          // 0..2047 (int4 = 8 bf16; 16 per row)
        int n = idx >> 4, q = idx & 15;
        dH[n * 17 + q] = srcH[idx];
        dL[n * 17 + q] = srcL[idx];
    }
}

// warp-tile mma: 64x32 per warp, K=128, 3 products. acc[4][4][4].
__device__ __forceinline__ void mma_tile(float acc[4][4][4], uint32_t sb,
                                         int warp_m, int warp_n, int lane) {
    // per-lane ldmatrix byte offsets
    int arow = warp_m * 64 + (lane & 15);
    int acolB = ((lane >> 4) * 8) * 2;                 // bytes
    int brow = warp_n * 32 + (lane & 7);
    int bcolB = (((lane >> 3) & 1) * 8) * 2;           // bytes
    uint32_t aoff = sb + OF_AH * 2 + arow * (SLD * 2) + acolB;
    uint32_t loff = sb + OF_AL * 2 + arow * (SLD * 2) + acolB;
    uint32_t boff = sb + OF_BH * 2 + brow * (SLD * 2) + bcolB;
    uint32_t moff = sb + OF_BL * 2 + brow * (SLD * 2) + bcolB;

#pragma unroll
    for (int ks = 0; ks < 8; ks++) {
        uint32_t kbB = ks * 16 * 2;
        uint32_t ah[4][4], al[4][4], bh[4][2], bl[4][2];
#pragma unroll
        for (int mt = 0; mt < 4; mt++) {
            uint32_t off = mt * 16 * (SLD * 2) + kbB;
            LDM_X4(ah[mt], aoff + off);
            LDM_X4(al[mt], loff + off);
        }
#pragma unroll
        for (int nt = 0; nt < 4; nt++) {
            uint32_t off = nt * 8 * (SLD * 2) + kbB;
            LDM_X2(bh[nt], boff + off);
            LDM_X2(bl[nt], moff + off);
        }
#pragma unroll
        for (int mt = 0; mt < 4; mt++)
#pragma unroll
            for (int nt = 0; nt < 4; nt++) {
                MMA_BF16(acc[mt][nt], ah[mt], bh[nt]);
                MMA_BF16(acc[mt][nt], al[mt], bh[nt]);
                MMA_BF16(acc[mt][nt], ah[mt], bl[nt]);
            }
    }
}

// ------------------------- pre-projection GEMM ------------------------------
// [g_Ps | g_Pt](N x 512) = emb(N x 128) @ Wfused(128 x 512)
__global__ __launch_bounds__(256) void gemm_pre_mma(const float* __restrict__ A, int M) {
    extern __shared__ char smc[];
    __nv_bfloat16* sm = (__nv_bfloat16*)smc;
    uint32_t sb = smem_u32(smc);
    int tid = threadIdx.x, lane = tid & 31, wid = tid >> 5;
    int rowBase = blockIdx.x * 128, yt = blockIdx.y;
    int warp_m = wid & 1, warp_n = wid >> 1;

    stage_B(sm + OF_BH, sm + OF_BL, g_BpreH + (size_t)yt * 16384,
            g_BpreL + (size_t)yt * 16384, tid);
    stage_A(sm + OF_AH, sm + OF_AL, A, rowBase, M, nullptr, tid);
    __syncthreads();

    float acc[4][4][4];
#pragma unroll
    for (int mt = 0; mt < 4; mt++)
#pragma unroll
        for (int nt = 0; nt < 4; nt++)
#pragma unroll
            for (int j = 0; j < 4; j++) acc[mt][nt][j] = 0.f;

    mma_tile(acc, sb, warp_m, warp_n, lane);

    float* Cbase;
    int colOff;
    if (yt < 2) { Cbase = g_Ps; colOff = yt * 128; }
    else        { Cbase = g_Pt; colOff = (yt - 2) * 128; }
    int grp = lane >> 2, qid = lane & 3;
#pragma unroll
    for (int mt = 0; mt < 4; mt++) {
#pragma unroll
        for (int nt = 0; nt < 4; nt++) {
            int c = colOff + warp_n * 32 + nt * 8 + qid * 2;
            int r0 = rowBase + warp_m * 64 + mt * 16 + grp;
            if (r0 < M)
                *(float2*)(Cbase + (size_t)r0 * 256 + c) =
                    make_float2(acc[mt][nt][0], acc[mt][nt][1]);
            int r1 = r0 + 8;
            if (r1 < M)
                *(float2*)(Cbase + (size_t)r1 * 256 + c) =
                    make_float2(acc[mt][nt][2], acc[mt][nt][3]);
        }
    }
}

// ------------------------- edge passes -------------------------------------
__global__ void edge_logits(const int* __restrict__ src, const int* __restrict__ dst, int E,
                            const float* __restrict__ w0b, const float* __restrict__ w1b) {
    int gw = (int)(((size_t)blockIdx.x * blockDim.x + threadIdx.x) >> 5);
    int lane = threadIdx.x & 31;
    if (gw >= E) return;
    int s = src[gw], t = dst[gw];
    const float4* ps = (const float4*)(g_Ps + (size_t)s * 256);
    const float4* pt = (const float4*)(g_Pt + (size_t)t * 256);
    const float4* bi = (const float4*)g_bias;
    const float4* wv = (const float4*)g_wv;

    float4 a = ps[lane], b = pt[lane], c = bi[lane], w = wv[lane];
    float s0 = fast_tanh(a.x + b.x + c.x) * w.x
             + fast_tanh(a.y + b.y + c.y) * w.y
             + fast_tanh(a.z + b.z + c.z) * w.z
             + fast_tanh(a.w + b.w + c.w) * w.w;

    a = ps[32 + lane]; b = pt[32 + lane]; c = bi[32 + lane]; w = wv[32 + lane];
    float s1 = fast_tanh(a.x + b.x + c.x) * w.x
             + fast_tanh(a.y + b.y + c.y) * w.y
             + fast_tanh(a.z + b.z + c.z) * w.z
             + fast_tanh(a.w + b.w + c.w) * w.w;

#pragma unroll
    for (int o = 16; o; o >>= 1) {
        s0 += __shfl_xor_sync(0xFFFFFFFFu, s0, o);
        s1 += __shfl_xor_sync(0xFFFFFFFFu, s1, o);
    }
    if (lane == 0) {
        float e0 = s0 + w0b[0];
        float e1 = s1 + w1b[0];
        g_logit0[gw] = e0;
        g_logit1[gw] = e1;
        // max clamped at 0 (torch include_self over zeros); int-bit atomicMax
        // valid since stored (0) and candidates (>0) are non-negative.
        if (e0 > 0.f) atomicMax((int*)(g_max0 + s), __float_as_int(e0));
        if (e1 > 0.f) atomicMax((int*)(g_max1 + t), __float_as_int(e1));
    }
}

__global__ void edge_exp(const int* __restrict__ src, const int* __restrict__ dst, int E) {
    int e = blockIdx.x * blockDim.x + threadIdx.x;
    if (e >= E) return;
    int s = src[e], t = dst[e];
    float p0 = fast_exp(g_logit0[e] - g_max0[s]);
    float p1 = fast_exp(g_logit1[e] - g_max1[t]);
    g_logit0[e] = p0;
    g_logit1[e] = p1;
    atomicAdd(g_sum0 + s, p0);
    atomicAdd(g_sum1 + t, p1);
}

__global__ void edge_scatter(const int* __restrict__ src, const int* __restrict__ dst, int E,
                             const float* __restrict__ emb) {
    int gw = (int)(((size_t)blockIdx.x * blockDim.x + threadIdx.x) >> 5);
    int lane = threadIdx.x & 31;
    if (gw >= E) return;
    int s = src[gw], t = dst[gw];
    float a0 = __fdividef(g_logit0[gw], g_sum0[s] + 1e-9f);
    float a1 = __fdividef(g_logit1[gw], g_sum1[t] + 1e-9f);
    const float4* emb4 = (const float4*)emb;

    float4 r = emb4[(size_t)t * 32 + lane];
    float* d0 = g_attn + (size_t)s * 128 + lane * 4;
    atomicAdd(d0 + 0, a0 * r.x); atomicAdd(d0 + 1, a0 * r.y);
    atomicAdd(d0 + 2, a0 * r.z); atomicAdd(d0 + 3, a0 * r.w);

    float4 h = emb4[(size_t)s * 32 + lane];
    float* d1 = g_attn + (size_t)t * 128 + lane * 4;
    atomicAdd(d1 + 0, a1 * h.x); atomicAdd(d1 + 1, a1 * h.y);
    atomicAdd(d1 + 2, a1 * h.z); atomicAdd(d1 + 3, a1 * h.w);
}

__global__ void mean_scatter(const int* __restrict__ src, const int* __restrict__ dst, int E,
                             const float* __restrict__ emb) {
    int gw = (int)(((size_t)blockIdx.x * blockDim.x + threadIdx.x) >> 5);
    int lane = threadIdx.x & 31;
    if (gw >= E) return;
    int s = src[gw], t = dst[gw];
    const float4* emb4 = (const float4*)emb;
    float4 v = emb4[(size_t)t * 32 + lane];
    float* d0 = g_mean + (size_t)s * 128 + lane * 4;
    atomicAdd(d0 + 0, v.x); atomicAdd(d0 + 1, v.y);
    atomicAdd(d0 + 2, v.z); atomicAdd(d0 + 3, v.w);
    if (lane == 0) atomicAdd(g_cnt + s, 1.0f);
}

// ------------------------- fused output GEMM --------------------------------
// out = tanh(emb@W1+b1) + tanh(attn@W2+b2) + tanh((mean/cnt)@W3+b3)
__global__ __launch_bounds__(256) void gemm_out_mma(const float* __restrict__ emb,
                                                    const float* __restrict__ b1,
                                                    const float* __restrict__ b2,
                                                    const float* __restrict__ b3,
                                                    float* __restrict__ out, int M) {
    extern __shared__ char smc[];
    __nv_bfloat16* sm = (__nv_bfloat16*)smc;
    float* sbias = (float*)(smc + SMEM_GEMM);
    uint32_t sb = smem_u32(smc);
    int tid = threadIdx.x, lane = tid & 31, wid = tid >> 5;
    int rowBase = blockIdx.x * 128;
    int warp_m = wid & 1, warp_n = wid >> 1;
    int grp = lane >> 2, qid = lane & 3;

    if (tid < 128) {
        sbias[tid]       = b1[tid];
        sbias[128 + tid] = b2[tid];
        sbias[256 + tid] = b3[tid];
    }

    float res[4][4][4];
#pragma unroll
    for (int mt = 0; mt < 4; mt++)
#pragma unroll
        for (int nt = 0; nt < 4; nt++)
#pragma unroll
            for (int j = 0; j < 4; j++) res[mt][nt][j] = 0.f;

#pragma unroll 1
    for (int t = 0; t < 3; t++) {
        const float* Abase = (t == 0) ? emb : (t == 1) ? g_attn : g_mean;
        stage_B(sm + OF_BH, sm + OF_BL, g_BoutH + (size_t)t * 16384,
                g_BoutL + (size_t)t * 16384, tid);
        stage_A(sm + OF_AH, sm + OF_AL, Abase, rowBase, M,
                (t == 2) ? g_cnt : nullptr, tid);
        __syncthreads();

        float acc[4][4][4];
#pragma unroll
        for (int mt = 0; mt < 4; mt++)
#pragma unroll
            for (int nt = 0; nt < 4; nt++)
#pragma unroll
                for (int j = 0; j < 4; j++) acc[mt][nt][j] = 0.f;

        mma_tile(acc, sb, warp_m, warp_n, lane);

        const float* bias = sbias + t * 128;
#pragma unroll
        for (int mt = 0; mt < 4; mt++)
#pragma unroll
            for (int nt = 0; nt < 4; nt++) {
                int c = warp_n * 32 + nt * 8 + qid * 2;
                float bv0 = bias[c], bv1 = bias[c + 1];
                res[mt][nt][0] += fast_tanh(acc[mt][nt][0] + bv0);
                res[mt][nt][1] += fast_tanh(acc[mt][nt][1] + bv1);
                res[mt][nt][2] += fast_tanh(acc[mt][nt][2] + bv0);
                res[mt][nt][3] += fast_tanh(acc[mt][nt][3] + bv1);
            }
        __syncthreads();
    }

#pragma unroll
    for (int mt = 0; mt < 4; mt++)
#pragma unroll
        for (int nt = 0; nt < 4; nt++) {
            int c = warp_n * 32 + nt * 8 + qid * 2;
            int r0 = rowBase + warp_m * 64 + mt * 16 + grp;
            if (r0 < M)
                *(float2*)(out + (size_t)r0 * 128 + c) =
                    make_float2(res[mt][nt][0], res[mt][nt][1]);
            int r1 = r0 + 8;
            if (r1 < M)
                *(float2*)(out + (size_t)r1 * 128 + c) =
                    make_float2(res[mt][nt][2], res[mt][nt][3]);
        }
}

// ------------------------- launch ------------------------------------------
extern "C" void kernel_launch(void* const* d_in, const int* in_sizes, int n_in,
                              void* d_out, int out_size) {
    const float* emb = (const float*)d_in[0];
    const float* Wae = (const float*)d_in[1];
    const float* bae = (const float*)d_in[2];
    const float* w0w = (const float*)d_in[3];
    const float* w0b = (const float*)d_in[4];
    const float* War = (const float*)d_in[5];
    const float* bar = (const float*)d_in[6];
    const float* w1w = (const float*)d_in[7];
    const float* w1b = (const float*)d_in[8];
    const float* W1  = (const float*)d_in[9];
    const float* b1  = (const float*)d_in[10];
    const float* W2  = (const float*)d_in[11];
    const float* b2  = (const float*)d_in[12];
    const float* W3  = (const float*)d_in[13];
    const float* b3  = (const float*)d_in[14];
    const int* er_src = (const int*)d_in[15];
    const int* er_dst = (const int*)d_in[16];
    const int* ee_src = (const int*)d_in[17];
    const int* ee_dst = (const int*)d_in[18];
    const int* rr_src = (const int*)d_in[19];
    const int* rr_dst = (const int*)d_in[20];

    int N   = in_sizes[0] / 128;
    int Eer = in_sizes[15];
    int Eee = in_sizes[17];
    int Err = in_sizes[19];
    float* out = (float*)d_out;

    cudaFuncSetAttribute(gemm_pre_mma, cudaFuncAttributeMaxDynamicSharedMemorySize, SMEM_GEMM);
    cudaFuncSetAttribute(gemm_out_mma, cudaFuncAttributeMaxDynamicSharedMemorySize, SMEM_GEMM_OUT);

    zero_all<<<2048, 256>>>(N);
    prep_kernel<<<(65536 + 49152 + 255) / 256, 256>>>(Wae, War, bae, bar, w0w, w1w, W1, W2, W3);

    dim3 gpre((N + 127) / 128, 4);
    gemm_pre_mma<<<gpre, 256, SMEM_GEMM>>>(emb, N);

    int wblk_er = (Eer + 7) / 8;  // 8 warps per 256-thread block
    edge_logits<<<wblk_er, 256>>>(er_src, er_dst, Eer, w0b, w1b);
    edge_exp<<<(Eer + 255) / 256, 256>>>(er_src, er_dst, Eer);
    edge_scatter<<<wblk_er, 256>>>(er_src, er_dst, Eer, emb);

    mean_scatter<<<(Eee + 7) / 8, 256>>>(ee_src, ee_dst, Eee, emb);
    mean_scatter<<<(Err + 7) / 8, 256>>>(rr_src, rr_dst, Err, emb);

    gemm_out_mma<<<(N + 127) / 128, 256, SMEM_GEMM_OUT>>>(emb, b1, b2, b3, out, N);
}